// round 1
// baseline (speedup 1.0000x reference)
#include <cuda_runtime.h>

// Problem constants
#define B_    4
#define C_    256
#define CQ_   32
#define MID_  16
#define H_    56
#define W_    56
#define HW_   3136     // 56*56 = 49*64
#define KK_   7

// Scratch (allocation-free: __device__ globals)
__device__ float g_wkq[64 * 256];          // packed [w_k; w_q] (64, 256)
__device__ float g_bkq[64];
__device__ float g_gpk[CQ_ * 49];          // geometry prior (CQ,7,7)
__device__ float g_kmqm[B_ * 64 * HW_];    // (B, 64, HW): ch<32 -> km, ch>=32 -> qm
__device__ float g_pre[B_ * C_ * HW_];     // (B, C, HW)

// ---------------------------------------------------------------------------
// Pack w_k/w_q (+biases) into a single 64x256 weight for one fused GEMM
__global__ void pack_kernel(const float* __restrict__ wk, const float* __restrict__ bk,
                            const float* __restrict__ wq, const float* __restrict__ bq) {
    int idx = blockIdx.x * 256 + threadIdx.x;
    if (idx < 64 * 256) {
        int oc = idx >> 8, cc = idx & 255;
        g_wkq[idx] = (oc < 32) ? wk[oc * 256 + cc] : wq[(oc - 32) * 256 + cc];
    }
    if (idx < 64) g_bkq[idx] = (idx < 32) ? bk[idx] : bq[idx - 32];
}

// ---------------------------------------------------------------------------
// Geometry prior: gpk[c,i,j] = w_g2 @ relu(w_g1 @ pos + b_g1) + b_g2
__global__ void gpk_kernel(const float* __restrict__ wg1, const float* __restrict__ bg1,
                           const float* __restrict__ wg2, const float* __restrict__ bg2) {
    int idx = blockIdx.x * 256 + threadIdx.x;
    if (idx >= CQ_ * 49) return;
    int c = idx / 49, r = idx % 49, i = r / 7, j = r % 7;
    float xp = (float)(j - 3);   // x_pos = a[j] = j - 3
    float yp = (float)(3 - i);   // y_pos = b_r[i] = 3 - i
    float acc = bg2[c];
#pragma unroll
    for (int o = 0; o < MID_; o++) {
        float g1 = fmaf(wg1[o * 2 + 0], xp, fmaf(wg1[o * 2 + 1], yp, bg1[o]));
        g1 = fmaxf(g1, 0.f);
        acc = fmaf(wg2[c * MID_ + o], g1, acc);
    }
    g_gpk[idx] = acc;
}

// ---------------------------------------------------------------------------
// Batched SGEMM: Out[b, oc, p] = sum_c W[oc, c] * In[b, c, p] + bias[oc]
// BM=BN=64, BK=16, 256 threads, 4x4 microtile. Requires HW_%64==0, OC%64==0, Cdim%16==0.
__global__ void __launch_bounds__(256) gemm_kernel(
    const float* __restrict__ W, const float* __restrict__ bias,
    const float* __restrict__ In, float* __restrict__ Out,
    int Cdim, int OC) {
    __shared__ float As[16][64];
    __shared__ float Bs[16][64];

    int b = blockIdx.z;
    const float* Inb = In + (size_t)b * Cdim * HW_;
    float* Outb = Out + (size_t)b * OC * HW_;
    int ocBase = blockIdx.y * 64;
    int pBase  = blockIdx.x * 64;

    int tid = threadIdx.x;
    int tx = tid & 15, ty = tid >> 4;

    float acc[4][4];
#pragma unroll
    for (int i = 0; i < 4; i++)
#pragma unroll
        for (int j = 0; j < 4; j++) acc[i][j] = 0.f;

    int am = tid >> 2, ak = (tid & 3) << 2;     // A: 256 float4 loads -> As[k][m]
    int bk = tid >> 4, bn = (tid & 15) << 2;    // B: 256 float4 loads -> Bs[k][n]
    const float* wptr = W + (size_t)(ocBase + am) * Cdim + ak;
    const float* iptr = Inb + (size_t)bk * HW_ + pBase + bn;

    for (int k0 = 0; k0 < Cdim; k0 += 16) {
        float4 av = *(const float4*)(wptr + k0);
        As[ak + 0][am] = av.x;
        As[ak + 1][am] = av.y;
        As[ak + 2][am] = av.z;
        As[ak + 3][am] = av.w;
        *(float4*)&Bs[bk][bn] = *(const float4*)(iptr + (size_t)k0 * HW_);
        __syncthreads();
#pragma unroll
        for (int kk = 0; kk < 16; kk++) {
            float4 a  = *(const float4*)&As[kk][ty * 4];
            float4 bb = *(const float4*)&Bs[kk][tx * 4];
            acc[0][0] = fmaf(a.x, bb.x, acc[0][0]);
            acc[0][1] = fmaf(a.x, bb.y, acc[0][1]);
            acc[0][2] = fmaf(a.x, bb.z, acc[0][2]);
            acc[0][3] = fmaf(a.x, bb.w, acc[0][3]);
            acc[1][0] = fmaf(a.y, bb.x, acc[1][0]);
            acc[1][1] = fmaf(a.y, bb.y, acc[1][1]);
            acc[1][2] = fmaf(a.y, bb.z, acc[1][2]);
            acc[1][3] = fmaf(a.y, bb.w, acc[1][3]);
            acc[2][0] = fmaf(a.z, bb.x, acc[2][0]);
            acc[2][1] = fmaf(a.z, bb.y, acc[2][1]);
            acc[2][2] = fmaf(a.z, bb.z, acc[2][2]);
            acc[2][3] = fmaf(a.z, bb.w, acc[2][3]);
            acc[3][0] = fmaf(a.w, bb.x, acc[3][0]);
            acc[3][1] = fmaf(a.w, bb.y, acc[3][1]);
            acc[3][2] = fmaf(a.w, bb.z, acc[3][2]);
            acc[3][3] = fmaf(a.w, bb.w, acc[3][3]);
        }
        __syncthreads();
    }

#pragma unroll
    for (int i = 0; i < 4; i++) {
        float bo = bias[ocBase + ty * 4 + i];
        float4 r = make_float4(acc[i][0] + bo, acc[i][1] + bo, acc[i][2] + bo, acc[i][3] + bo);
        *(float4*)&Outb[(size_t)(ocBase + ty * 4 + i) * HW_ + pBase + tx * 4] = r;
    }
}

// ---------------------------------------------------------------------------
// Attention: per (b, c in [0,32), pixel p):
//   ak[i][j] = km[yy,xx]*q_center + gpk[c,i,j]   (km OOB -> 0, so ak = gpk)
//   ck = softmax over j (last dim only!)
//   pre[b, g*32+c, p] = sum_{i,j} ck * x[b, g*32+c, yy, xx]  (x OOB -> 0)
__global__ void __launch_bounds__(224) attn_kernel(const float* __restrict__ x) {
    int b = blockIdx.z, c = blockIdx.y;
    int p = blockIdx.x * 224 + threadIdx.x;
    int y = p / W_, xc = p % W_;

    const float* km = g_kmqm + (size_t)(b * 64 + c) * HW_;
    float qv = g_kmqm[(size_t)(b * 64 + 32 + c) * HW_ + p];
    const float* gp = g_gpk + c * 49;
    const float* xb = x + (size_t)(b * C_ + c) * HW_;   // group stride = 32*HW_

    float acc[8];
#pragma unroll
    for (int g = 0; g < 8; g++) acc[g] = 0.f;

#pragma unroll
    for (int i = 0; i < 7; i++) {
        int yy = y + i - 3;
        if ((unsigned)yy >= (unsigned)H_) continue;  // entire row's x is zero-padded
        float a[7];
        float mx = -1e30f;
#pragma unroll
        for (int j = 0; j < 7; j++) {
            int xx = xc + j - 3;
            float kmv = ((unsigned)xx < (unsigned)W_) ? km[yy * W_ + xx] : 0.f;
            float av = fmaf(kmv, qv, gp[i * 7 + j]);
            a[j] = av;
            mx = fmaxf(mx, av);
        }
        float s = 0.f;
#pragma unroll
        for (int j = 0; j < 7; j++) { a[j] = __expf(a[j] - mx); s += a[j]; }
        float inv = __frcp_rn(s);
        const float* xr = xb + yy * W_;
#pragma unroll
        for (int j = 0; j < 7; j++) {
            int xx = xc + j - 3;
            if ((unsigned)xx < (unsigned)W_) {
                float w = a[j] * inv;
#pragma unroll
                for (int g = 0; g < 8; g++)
                    acc[g] = fmaf(w, xr[(size_t)g * 32 * HW_ + xx], acc[g]);
            }
        }
    }

    float* pr = g_pre + (size_t)(b * C_ + c) * HW_ + p;
#pragma unroll
    for (int g = 0; g < 8; g++) pr[(size_t)g * 32 * HW_] = acc[g];
}

// ---------------------------------------------------------------------------
extern "C" void kernel_launch(void* const* d_in, const int* in_sizes, int n_in,
                              void* d_out, int out_size) {
    const float* x    = (const float*)d_in[0];
    const float* w_k  = (const float*)d_in[1];
    const float* b_k  = (const float*)d_in[2];
    const float* w_q  = (const float*)d_in[3];
    const float* b_q  = (const float*)d_in[4];
    const float* w_g1 = (const float*)d_in[5];
    const float* b_g1 = (const float*)d_in[6];
    const float* w_g2 = (const float*)d_in[7];
    const float* b_g2 = (const float*)d_in[8];
    const float* w_f  = (const float*)d_in[9];
    const float* b_f  = (const float*)d_in[10];
    float* out = (float*)d_out;

    float *wkq, *bkq, *kmqm, *pre;
    cudaGetSymbolAddress((void**)&wkq,  g_wkq);
    cudaGetSymbolAddress((void**)&bkq,  g_bkq);
    cudaGetSymbolAddress((void**)&kmqm, g_kmqm);
    cudaGetSymbolAddress((void**)&pre,  g_pre);

    pack_kernel<<<64, 256>>>(w_k, b_k, w_q, b_q);
    gpk_kernel<<<7, 256>>>(w_g1, b_g1, w_g2, b_g2);
    // km/qm 1x1 conv: (64 x 256) @ (256 x HW) per batch
    gemm_kernel<<<dim3(HW_ / 64, 1, B_), 256>>>(wkq, bkq, x, kmqm, C_, 64);
    // attention + aggregation -> pre
    attn_kernel<<<dim3(HW_ / 224, CQ_, B_), 224>>>(x);
    // final 1x1 conv: (256 x 256) @ (256 x HW) per batch
    gemm_kernel<<<dim3(HW_ / 64, C_ / 64, B_), 256>>>(w_f, b_f, pre, out, C_, C_);
}

// round 2
// speedup vs baseline: 1.0830x; 1.0830x over previous
#include <cuda_runtime.h>

// Problem constants
#define B_    4
#define C_    256
#define CQ_   32
#define MID_  16
#define H_    56
#define W_    56
#define HW_   3136     // 56*56
#define KK_   7

// Scratch (allocation-free: __device__ globals)
__device__ float g_gpk[CQ_ * 49];          // geometry prior (CQ,7,7)
__device__ float g_kmqm[B_ * 64 * HW_];    // (B, 64, HW): ch<32 -> km, ch>=32 -> qm
__device__ float g_pre[B_ * C_ * HW_];     // (B, C, HW)

// ---------------------------------------------------------------------------
// Geometry prior: gpk[c,i,j] = w_g2 @ relu(w_g1 @ pos + b_g1) + b_g2
__global__ void gpk_kernel(const float* __restrict__ wg1, const float* __restrict__ bg1,
                           const float* __restrict__ wg2, const float* __restrict__ bg2) {
    int idx = blockIdx.x * 256 + threadIdx.x;
    if (idx >= CQ_ * 49) return;
    int c = idx / 49, r = idx % 49, i = r / 7, j = r % 7;
    float xp = (float)(j - 3);   // x_pos
    float yp = (float)(3 - i);   // y_pos
    float acc = bg2[c];
#pragma unroll
    for (int o = 0; o < MID_; o++) {
        float g1 = fmaf(wg1[o * 2 + 0], xp, fmaf(wg1[o * 2 + 1], yp, bg1[o]));
        g1 = fmaxf(g1, 0.f);
        acc = fmaf(wg2[c * MID_ + o], g1, acc);
    }
    g_gpk[idx] = acc;
}

// ---------------------------------------------------------------------------
// Double-buffered SGEMM: Out[b, oc, p] = sum_c Wrow(oc)[c] * In[b, c, p] + bias(oc)
// Weight rows oc < split come from W1, else W2 (lets km/qm share one GEMM).
// BM in {64,128}, BN=64, BK=16, 256 threads, (BM/16)x4 microtile.
template<int BM>
__global__ void __launch_bounds__(256) gemm2(
    const float* __restrict__ W1, const float* __restrict__ W2, int split,
    const float* __restrict__ bias1, const float* __restrict__ bias2,
    const float* __restrict__ In, float* __restrict__ Out, int Cdim, int OC) {
    constexpr int TM = BM / 16;     // 4 or 8
    constexpr int NA = TM / 4;      // 1 or 2 float4 A-loads per thread
    __shared__ float As[2][16][BM];
    __shared__ float Bs[2][16][64];

    int b = blockIdx.z;
    const float* Inb = In + (size_t)b * Cdim * HW_;
    float* Outb = Out + (size_t)b * OC * HW_;
    int ocBase = blockIdx.y * BM;
    int pBase  = blockIdx.x * 64;

    int tid = threadIdx.x;
    int tx = tid & 15, ty = tid >> 4;

    // A-load mapping
    int arow, akb;
    if (BM == 128) { arow = tid >> 1; akb = (tid & 1) * 8; }
    else           { arow = tid >> 2; akb = (tid & 3) * 4; }
    int oc = ocBase + arow;
    const float* wrow = (oc < split) ? (W1 + (size_t)oc * Cdim)
                                     : (W2 + (size_t)(oc - split) * Cdim);
    // B-load mapping
    int brow = tid >> 4, bcol = (tid & 15) * 4;
    const float* bptr = Inb + (size_t)brow * HW_ + pBase + bcol;

    float acc[TM][4];
#pragma unroll
    for (int i = 0; i < TM; i++)
#pragma unroll
        for (int j = 0; j < 4; j++) acc[i][j] = 0.f;

    float4 aR[NA], bR;

    // prologue: fetch + store stage 0
#pragma unroll
    for (int u = 0; u < NA; u++)
        aR[u] = *(const float4*)(wrow + akb + 4 * u);
    bR = *(const float4*)(bptr);
#pragma unroll
    for (int u = 0; u < NA; u++) {
        As[0][akb + 4 * u + 0][arow] = aR[u].x;
        As[0][akb + 4 * u + 1][arow] = aR[u].y;
        As[0][akb + 4 * u + 2][arow] = aR[u].z;
        As[0][akb + 4 * u + 3][arow] = aR[u].w;
    }
    *(float4*)&Bs[0][brow][bcol] = bR;
    __syncthreads();

    int cur = 0;
    for (int k0 = 0; k0 < Cdim; k0 += 16) {
        bool nxt = (k0 + 16) < Cdim;
        if (nxt) {
#pragma unroll
            for (int u = 0; u < NA; u++)
                aR[u] = *(const float4*)(wrow + k0 + 16 + akb + 4 * u);
            bR = *(const float4*)(bptr + (size_t)(k0 + 16) * HW_);
        }
#pragma unroll
        for (int kk = 0; kk < 16; kk++) {
            float a[TM];
#pragma unroll
            for (int v = 0; v < NA; v++)
                *(float4*)&a[4 * v] = *(const float4*)&As[cur][kk][ty * TM + 4 * v];
            float4 b4 = *(const float4*)&Bs[cur][kk][tx * 4];
#pragma unroll
            for (int i = 0; i < TM; i++) {
                acc[i][0] = fmaf(a[i], b4.x, acc[i][0]);
                acc[i][1] = fmaf(a[i], b4.y, acc[i][1]);
                acc[i][2] = fmaf(a[i], b4.z, acc[i][2]);
                acc[i][3] = fmaf(a[i], b4.w, acc[i][3]);
            }
        }
        if (nxt) {
            int s = cur ^ 1;
#pragma unroll
            for (int u = 0; u < NA; u++) {
                As[s][akb + 4 * u + 0][arow] = aR[u].x;
                As[s][akb + 4 * u + 1][arow] = aR[u].y;
                As[s][akb + 4 * u + 2][arow] = aR[u].z;
                As[s][akb + 4 * u + 3][arow] = aR[u].w;
            }
            *(float4*)&Bs[s][brow][bcol] = bR;
            __syncthreads();
            cur = s;
        }
    }

#pragma unroll
    for (int i = 0; i < TM; i++) {
        int oc2 = ocBase + ty * TM + i;
        float bo = (oc2 < split) ? bias1[oc2] : bias2[oc2 - split];
        float4 r = make_float4(acc[i][0] + bo, acc[i][1] + bo,
                               acc[i][2] + bo, acc[i][3] + bo);
        *(float4*)&Outb[(size_t)oc2 * HW_ + pBase + tx * 4] = r;
    }
}

// ---------------------------------------------------------------------------
// Attention, smem-tiled, 2 pixels/thread.
// Block = 8-row strip x 56 cols (224 threads); smem holds km + 8 x-group planes
// as 14 rows x 64 cols (3-left/5-right zero padding), OOB pre-zeroed.
// Zero-padded km rows/cols reproduce the reference exactly: padded km enters the
// row softmax as gpk alone, and padded x contributes 0 to the aggregation.
__global__ void __launch_bounds__(224) attn_kernel(const float* __restrict__ x) {
    __shared__ float s_all[9][14][64];   // plane 0 = km, 1+g = x group g
    __shared__ float s_gp[49];

    int b = blockIdx.z, c = blockIdx.y;
    int y0 = blockIdx.x * 8;
    int tid = threadIdx.x;

    if (tid < 49) s_gp[tid] = g_gpk[c * 49 + tid];

    const float* kmp = g_kmqm + (size_t)(b * 64 + c) * HW_;
    float* s_flat = &s_all[0][0][0];
    for (int idx = tid; idx < 9 * 14 * 64; idx += 224) {
        int plane = idx / 896;
        int rem = idx - plane * 896;
        int r = rem >> 6, coli = rem & 63;
        int yy = y0 - 3 + r, xx = coli - 3;
        float v = 0.f;
        if ((unsigned)yy < (unsigned)H_ && (unsigned)xx < (unsigned)W_) {
            const float* src = (plane == 0) ? kmp
                : x + (size_t)(b * C_ + (plane - 1) * 32 + c) * HW_;
            v = src[yy * W_ + xx];
        }
        s_flat[idx] = v;
    }
    __syncthreads();

    int tr = tid / 28;            // 0..7
    int tc = (tid - tr * 28) * 2; // even 0..54
    int y = y0 + tr;
    int p = y * W_ + tc;

    float2 qv = *(const float2*)(g_kmqm + (size_t)(b * 64 + 32 + c) * HW_ + p);

    float acc0[8], acc1[8];
#pragma unroll
    for (int g = 0; g < 8; g++) { acc0[g] = 0.f; acc1[g] = 0.f; }

#pragma unroll
    for (int i = 0; i < 7; i++) {
        int si = tr + i;
        float kw[8];
#pragma unroll
        for (int u = 0; u < 4; u++)
            *(float2*)&kw[2 * u] = *(const float2*)&s_all[0][si][tc + 2 * u];

        float w0[7], w1[7];
        float s0 = 0.f, s1 = 0.f;
#pragma unroll
        for (int j = 0; j < 7; j++) {
            float gp = s_gp[i * 7 + j];
            w0[j] = __expf(fmaf(kw[j],     qv.x, gp)); s0 += w0[j];
            w1[j] = __expf(fmaf(kw[j + 1], qv.y, gp)); s1 += w1[j];
        }
        float i0 = __frcp_rn(s0), i1 = __frcp_rn(s1);
#pragma unroll
        for (int j = 0; j < 7; j++) { w0[j] *= i0; w1[j] *= i1; }

#pragma unroll
        for (int g = 0; g < 8; g++) {
            float xw[8];
#pragma unroll
            for (int u = 0; u < 4; u++)
                *(float2*)&xw[2 * u] = *(const float2*)&s_all[1 + g][si][tc + 2 * u];
#pragma unroll
            for (int j = 0; j < 7; j++) {
                acc0[g] = fmaf(w0[j], xw[j],     acc0[g]);
                acc1[g] = fmaf(w1[j], xw[j + 1], acc1[g]);
            }
        }
    }

    float* pr = g_pre + (size_t)(b * C_ + c) * HW_ + p;
#pragma unroll
    for (int g = 0; g < 8; g++)
        *(float2*)(pr + (size_t)g * 32 * HW_) = make_float2(acc0[g], acc1[g]);
}

// ---------------------------------------------------------------------------
extern "C" void kernel_launch(void* const* d_in, const int* in_sizes, int n_in,
                              void* d_out, int out_size) {
    const float* x    = (const float*)d_in[0];
    const float* w_k  = (const float*)d_in[1];
    const float* b_k  = (const float*)d_in[2];
    const float* w_q  = (const float*)d_in[3];
    const float* b_q  = (const float*)d_in[4];
    const float* w_g1 = (const float*)d_in[5];
    const float* b_g1 = (const float*)d_in[6];
    const float* w_g2 = (const float*)d_in[7];
    const float* b_g2 = (const float*)d_in[8];
    const float* w_f  = (const float*)d_in[9];
    const float* b_f  = (const float*)d_in[10];
    float* out = (float*)d_out;

    float *kmqm, *pre;
    cudaGetSymbolAddress((void**)&kmqm, g_kmqm);
    cudaGetSymbolAddress((void**)&pre,  g_pre);

    gpk_kernel<<<7, 256>>>(w_g1, b_g1, w_g2, b_g2);
    // km/qm 1x1 conv: rows 0..31 from w_k, 32..63 from w_q
    gemm2<64><<<dim3(HW_ / 64, 1, B_), 256>>>(w_k, w_q, 32, b_k, b_q, x, kmqm, C_, 64);
    // attention + aggregation -> pre
    attn_kernel<<<dim3(H_ / 8, CQ_, B_), 224>>>(x);
    // final 1x1 conv: (256 x 256) @ (256 x HW) per batch
    gemm2<128><<<dim3(HW_ / 64, C_ / 128, B_), 256>>>(w_f, w_f, C_, b_f, b_f, pre, out, C_, C_);
}